// round 4
// baseline (speedup 1.0000x reference)
#include <cuda_runtime.h>
#include <cuda_bf16.h>
#include <cstdint>

// ============================ PTX helpers (non-'a' target safe) ============================
__device__ __forceinline__ uint32_t smem_to_u32(const void* smem_ptr) {
    uint32_t addr;
    asm("{ .reg .u64 tmp; cvta.to.shared.u64 tmp, %1; cvt.u32.u64 %0, tmp; }"
        : "=r"(addr) : "l"(smem_ptr));
    return addr;
}

#define CP_ASYNC16(dst_u32, src_ptr) \
    asm volatile("cp.async.cg.shared.global [%0], [%1], 16;" \
                 :: "r"(dst_u32), "l"(src_ptr) : "memory")
#define CP_COMMIT() asm volatile("cp.async.commit_group;" ::: "memory")
#define CP_WAIT0()  asm volatile("cp.async.wait_group 0;" ::: "memory")

#define LDSM_X4(r0, r1, r2, r3, addr) \
    asm volatile("ldmatrix.sync.aligned.m8n8.x4.shared.b16 {%0,%1,%2,%3}, [%4];" \
                 : "=r"(r0), "=r"(r1), "=r"(r2), "=r"(r3) : "r"(addr))

#define MMA16816(d, a, b0, b1) \
    asm volatile("mma.sync.aligned.m16n8k16.row.col.f32.bf16.bf16.f32 " \
                 "{%0,%1,%2,%3}, {%4,%5,%6,%7}, {%8,%9}, {%0,%1,%2,%3};" \
                 : "+f"((d)[0]), "+f"((d)[1]), "+f"((d)[2]), "+f"((d)[3]) \
                 : "r"((a)[0]), "r"((a)[1]), "r"((a)[2]), "r"((a)[3]), \
                   "r"(b0), "r"(b1))

__device__ __forceinline__ uint32_t swz128(uint32_t off) {
    return off ^ ((off >> 3) & 0x70);
}
__device__ __forceinline__ uint32_t pack_bf16x2(__nv_bfloat16 a, __nv_bfloat16 b) {
    __nv_bfloat162 t = __halves2bfloat162(a, b);  // a -> low 16 bits
    return *reinterpret_cast<uint32_t*>(&t);
}
__device__ __forceinline__ uint32_t pack_f2bf(float a, float b) {
    __nv_bfloat162 t = __floats2bfloat162_rn(a, b);
    return *reinterpret_cast<uint32_t*>(&t);
}

// ============================ problem constants ============================
static constexpr int NTOK   = 8192;
static constexpr int FEAT   = 128;
static constexpr int KC     = 64;              // k per B-chunk (64 bf16 = 128B row)
static constexpr int NCHUNK = NTOK / KC;       // 128
static constexpr int CHUNK_BYTES = FEAT * 128; // 16384
static constexpr int TM     = 64;              // CTA M tile
static constexpr int KSTEP  = 128;             // k per pipeline stage (2 chunks)
static constexpr int NSTAGE = NTOK / KSTEP;    // 64
static constexpr int STG    = 98304;           // stage bytes: A 32K (hi16+lo16) + B 64K (hi32+lo32)

// ============================ device scratch ============================
__device__ __align__(16) unsigned char g_xwT_hi[NCHUNK * CHUNK_BYTES];  // 2 MB
__device__ __align__(16) unsigned char g_xwT_lo[NCHUNK * CHUNK_BYTES];
__device__ __align__(16) unsigned char g_B2_hi [NCHUNK * CHUNK_BYTES];
__device__ __align__(16) unsigned char g_B2_lo [NCHUNK * CHUNK_BYTES];
__device__ __align__(16) float g_scale[NTOK];

// ============================ kernel 1: xw = x @ W, split, chunk layout ============================
__global__ void xw_kernel(const float* __restrict__ x, const float* __restrict__ W) {
    extern __shared__ float sh[];
    float* Ws = sh;             // 128*128
    float* xs = sh + 16384;     // 16*128
    const int t = threadIdx.x;  // 0..127 (n index)
    const int rowbase = blockIdx.x * 16;

    for (int i = t; i < 16384; i += 128) Ws[i] = W[i];
    for (int i = t; i < 2048;  i += 128) xs[i] = x[(size_t)rowbase * 128 + i];
    __syncthreads();

    #pragma unroll 1
    for (int r2 = 0; r2 < 8; r2++) {
        float a0 = 0.f, a1 = 0.f;
        const float* x0 = xs + (2 * r2) * 128;
        const float* x1 = x0 + 128;
        #pragma unroll 8
        for (int k = 0; k < 128; k++) {
            float w = Ws[k * 128 + t];
            a0 = fmaf(x0[k], w, a0);
            a1 = fmaf(x1[k], w, a1);
        }
        int kg = rowbase + 2 * r2;
        int chunk = kg >> 6;
        int c = kg & 63;
        uint32_t off = swz128((uint32_t)t * 128u + (uint32_t)c * 2u);
        __nv_bfloat16 h0 = __float2bfloat16_rn(a0);
        __nv_bfloat16 h1 = __float2bfloat16_rn(a1);
        float l0 = a0 - __bfloat162float(h0);
        float l1 = a1 - __bfloat162float(h1);
        *(uint32_t*)(g_xwT_hi + (size_t)chunk * CHUNK_BYTES + off) = pack_bf16x2(h0, h1);
        *(uint32_t*)(g_xwT_lo + (size_t)chunk * CHUNK_BYTES + off) = pack_f2bf(l0, l1);
    }
}

// ============================ kernel 2: scale = sum_j d^2 * f ============================
__global__ void scale_kernel(const float* __restrict__ d_list, const float* __restrict__ filt) {
    int n = blockIdx.x * 256 + threadIdx.x;
    float s = 0.f;
    #pragma unroll
    for (int j = 0; j < 3; j++) {
        float d = d_list[j * NTOK + n];
        float f = filt[j * NTOK + n];
        s = fmaf(d * d, f, s);
    }
    g_scale[n] = s;
}

// ============================ fused GEMM: 64x128 C tile, full K, bf16 hi/lo split ============================
// grid 128, block 256 (8 warps as 2m x 4n, warp tile 32x32), smem 2 x 96KB stages
// Stage layout: [0,16K) A_hi (2 sub-chunks of 64x64) | [16K,32K) A_lo
//               [32K,64K) B_hi (2 chunks)            | [64K,96K) B_lo
__global__ __launch_bounds__(256, 1)
void gemm_fused_kernel(const float* __restrict__ A, const float* __restrict__ bias,
                       float* __restrict__ out, int phase) {
    extern __shared__ unsigned char dynsmem[];

    const unsigned char* Bhi = phase ? g_B2_hi : g_xwT_hi;
    const unsigned char* Blo = phase ? g_B2_lo : g_xwT_lo;

    const int tid = threadIdx.x;
    const int wid = tid >> 5;
    const int lid = tid & 31;
    const int mb = blockIdx.x * TM;

    const int wm = (wid >> 2) * 32;   // 0 or 32
    const int wn = (wid & 3) * 32;    // 0,32,64,96

    uint32_t smem_u = smem_to_u32(dynsmem);
    uint32_t base = (smem_u + 1023u) & ~1023u;
    unsigned char* sb = dynsmem + (base - smem_u);

    float acc[2][4][4];
    #pragma unroll
    for (int i = 0; i < 2; i++)
        #pragma unroll
        for (int j = 0; j < 4; j++)
            #pragma unroll
            for (int q = 0; q < 4; q++) acc[i][j][q] = 0.f;

    float4 aReg[8];

    auto ldg_stage = [&](int s) {
        #pragma unroll
        for (int i = 0; i < 8; i++) {
            int idx = tid + i * 256;          // 0..2047 float4 slots (64 rows x 32)
            int row = idx >> 5;
            int c4 = idx & 31;
            const float* src = A + (size_t)(mb + row) * NTOK + s * KSTEP + c4 * 4;
            aReg[i] = *reinterpret_cast<const float4*>(src);
        }
    };
    auto cpasync_b = [&](int s, int st) {
        uint32_t dsth = base + st * STG + 32768;
        uint32_t dstl = base + st * STG + 65536;
        const unsigned char* bh = Bhi + (size_t)s * 32768;
        const unsigned char* bl = Blo + (size_t)s * 32768;
        #pragma unroll
        for (int i = 0; i < 8; i++) {
            int off = (tid + i * 256) * 16;
            CP_ASYNC16(dsth + off, bh + off);
            CP_ASYNC16(dstl + off, bl + off);
        }
        CP_COMMIT();
    };
    auto sts_a = [&](int st) {
        unsigned char* stp = sb + st * STG;
        #pragma unroll
        for (int i = 0; i < 8; i++) {
            int idx = tid + i * 256;
            int row = idx >> 5;
            int c4 = idx & 31;
            int kc = c4 >> 4;                 // sub-chunk 0/1
            int cc = (c4 & 15) * 4;           // col within sub-chunk (0..60)
            uint32_t o = swz128((uint32_t)(row * 128 + cc * 2));  // 8B aligned
            float4 v = aReg[i];
            __nv_bfloat16 hx = __float2bfloat16_rn(v.x);
            __nv_bfloat16 hy = __float2bfloat16_rn(v.y);
            __nv_bfloat16 hz = __float2bfloat16_rn(v.z);
            __nv_bfloat16 hw = __float2bfloat16_rn(v.w);
            float rx = v.x - __bfloat162float(hx);
            float ry = v.y - __bfloat162float(hy);
            float rz = v.z - __bfloat162float(hz);
            float rw = v.w - __bfloat162float(hw);
            *(uint2*)(stp + kc * 8192 + o)          = make_uint2(pack_bf16x2(hx, hy), pack_bf16x2(hz, hw));
            *(uint2*)(stp + 16384 + kc * 8192 + o)  = make_uint2(pack_f2bf(rx, ry), pack_f2bf(rz, rw));
        }
    };

    // per-lane ldmatrix address components
    const int l7  = lid & 7;
    const int mat = lid >> 3;
    const int a_row_off = l7 + (mat & 1) * 8;
    const int a_kb_add  = (mat >> 1) * 16;
    const int b_row_off = l7 + (mat >> 1) * 8;
    const int b_kb_add  = (mat & 1) * 16;

    auto compute_stage = [&](int st) {
        uint32_t sA = base + st * STG;
        uint32_t sB = sA + 32768;
        #pragma unroll
        for (int kk = 0; kk < 8; kk++) {
            const int kc = kk >> 2;
            const int kb = (kk & 3) * 32;
            uint32_t ah[2][4], al[2][4], bh[4][2], bl[4][2];
            #pragma unroll
            for (int i = 0; i < 2; i++) {
                int row = wm + i * 16 + a_row_off;
                uint32_t off = sA + kc * 8192 + (uint32_t)(row * 128) +
                               (uint32_t)((kb + a_kb_add) ^ ((row & 7) << 4));
                LDSM_X4(ah[i][0], ah[i][1], ah[i][2], ah[i][3], off);
                LDSM_X4(al[i][0], al[i][1], al[i][2], al[i][3], off + 16384);
            }
            #pragma unroll
            for (int g = 0; g < 2; g++) {
                int row = wn + g * 16 + b_row_off;
                uint32_t off = sB + kc * 16384 + (uint32_t)(row * 128) +
                               (uint32_t)((kb + b_kb_add) ^ ((row & 7) << 4));
                uint32_t r0, r1, r2, r3;
                LDSM_X4(r0, r1, r2, r3, off);
                bh[2 * g][0] = r0; bh[2 * g][1] = r1;
                bh[2 * g + 1][0] = r2; bh[2 * g + 1][1] = r3;
                LDSM_X4(r0, r1, r2, r3, off + 32768);
                bl[2 * g][0] = r0; bl[2 * g][1] = r1;
                bl[2 * g + 1][0] = r2; bl[2 * g + 1][1] = r3;
            }
            #pragma unroll
            for (int i = 0; i < 2; i++) {
                #pragma unroll
                for (int j = 0; j < 4; j++) {
                    MMA16816(acc[i][j], ah[i], bh[j][0], bh[j][1]);
                    MMA16816(acc[i][j], ah[i], bl[j][0], bl[j][1]);
                    MMA16816(acc[i][j], al[i], bh[j][0], bh[j][1]);
                }
            }
        }
    };

    // prologue: fill stage 0
    ldg_stage(0);
    cpasync_b(0, 0);
    sts_a(0);
    CP_WAIT0();
    __syncthreads();

    for (int i = 0; i < NSTAGE; i++) {
        int b = i & 1;
        if (i + 1 < NSTAGE) {
            ldg_stage(i + 1);
            cpasync_b(i + 1, b ^ 1);
        }
        compute_stage(b);
        if (i + 1 < NSTAGE) {
            sts_a(b ^ 1);
            CP_WAIT0();
        }
        __syncthreads();
    }

    if (phase == 0) {
        // epilogue 1: v = scale[m] * acc ; transpose via smem ; write B2 chunk hi/lo
        float* sT = reinterpret_cast<float*>(sb);   // [128 n][pitch 65] fp32 (33.3KB, stage0 area)
        #pragma unroll
        for (int i = 0; i < 2; i++) {
            int r = wm + i * 16 + (lid >> 2);
            float s0 = g_scale[mb + r];
            float s1 = g_scale[mb + r + 8];
            #pragma unroll
            for (int j = 0; j < 4; j++) {
                int c = wn + j * 8 + (lid & 3) * 2;
                sT[c * 65 + r]           = acc[i][j][0] * s0;
                sT[(c + 1) * 65 + r]     = acc[i][j][1] * s0;
                sT[c * 65 + r + 8]       = acc[i][j][2] * s1;
                sT[(c + 1) * 65 + r + 8] = acc[i][j][3] * s1;
            }
        }
        __syncthreads();
        unsigned char* dhi = g_B2_hi + (size_t)blockIdx.x * CHUNK_BYTES;
        unsigned char* dlo = g_B2_lo + (size_t)blockIdx.x * CHUNK_BYTES;
        #pragma unroll
        for (int w = 0; w < 16; w++) {
            int idx = tid + w * 256;       // 0..4095 : n (128) x pair (32)
            int n = idx >> 5;
            int p = idx & 31;
            float v0 = sT[n * 65 + 2 * p];
            float v1 = sT[n * 65 + 2 * p + 1];
            __nv_bfloat16 h0 = __float2bfloat16_rn(v0);
            __nv_bfloat16 h1 = __float2bfloat16_rn(v1);
            float l0 = v0 - __bfloat162float(h0);
            float l1 = v1 - __bfloat162float(h1);
            uint32_t o = swz128((uint32_t)(n * 128 + p * 4));
            *(uint32_t*)(dhi + o) = pack_bf16x2(h0, h1);
            *(uint32_t*)(dlo + o) = pack_f2bf(l0, l1);
        }
    } else {
        // epilogue 2: out = acc + bias
        #pragma unroll
        for (int i = 0; i < 2; i++) {
            int r = mb + wm + i * 16 + (lid >> 2);
            #pragma unroll
            for (int j = 0; j < 4; j++) {
                int c = wn + j * 8 + (lid & 3) * 2;
                float2 bb = *reinterpret_cast<const float2*>(bias + c);
                *reinterpret_cast<float2*>(out + (size_t)r * FEAT + c) =
                    make_float2(acc[i][j][0] + bb.x, acc[i][j][1] + bb.y);
                *reinterpret_cast<float2*>(out + (size_t)(r + 8) * FEAT + c) =
                    make_float2(acc[i][j][2] + bb.x, acc[i][j][3] + bb.y);
            }
        }
    }
}

// ============================ launch ============================
extern "C" void kernel_launch(void* const* d_in, const int* in_sizes, int n_in,
                              void* d_out, int out_size) {
    const float* x      = (const float*)d_in[0];
    const float* d_list = (const float*)d_in[1];
    const float* U      = (const float*)d_in[2];
    const float* Vt     = (const float*)d_in[3];
    const float* W      = (const float*)d_in[4];
    const float* filt   = (const float*)d_in[5];
    const float* bias   = (const float*)d_in[6];
    float* out = (float*)d_out;

    cudaFuncSetAttribute(xw_kernel, cudaFuncAttributeMaxDynamicSharedMemorySize, 73728);
    cudaFuncSetAttribute(gemm_fused_kernel, cudaFuncAttributeMaxDynamicSharedMemorySize, 197632);

    xw_kernel<<<512, 128, 73728>>>(x, W);                          // idx 0
    scale_kernel<<<32, 256>>>(d_list, filt);                       // idx 1
    scale_kernel<<<32, 256>>>(d_list, filt);                       // idx 2 (profiling shim)
    gemm_fused_kernel<<<128, 256, 197632>>>(Vt, bias, out, 0);     // idx 3  <- profile target A
    scale_kernel<<<32, 256>>>(d_list, filt);                       // idx 4 (profiling shim)
    gemm_fused_kernel<<<128, 256, 197632>>>(U, bias, out, 1);      // idx 5  <- profile target B
}